// round 3
// baseline (speedup 1.0000x reference)
#include <cuda_runtime.h>
#include <cuda_bf16.h>

// Problem constants
#define B_      32
#define NTRAJ   512
#define LAT     256
#define HID     1024
#define TT      10
#define ROWS768 768              // NTRAJ + LAT
#define MTOT    (B_*ROWS768)     // 24576 rows of ODE state

// ---------------- scratch (device globals: no runtime allocation allowed) ----
__device__ float g_x[MTOT*LAT];        // current state x
__device__ float g_stage[MTOT*LAT];    // RK4 stage input
__device__ float g_acc[MTOT*LAT];      // RK4 k-accumulator
__device__ float g_H[MTOT*HID];        // hidden activations (tanh output)
__device__ float g_mean[B_*LAT];
__device__ float g_rstd[B_*LAT];

__device__ __forceinline__ unsigned f2tf(float f){
    unsigned u; asm("cvt.rna.tf32.f32 %0, %1;" : "=r"(u) : "f"(f)); return u;
}
__device__ __forceinline__ float fast_tanh(float x){
    float y; asm("tanh.approx.f32 %0, %1;" : "=f"(y) : "f"(x)); return y;
}

// ---------------- stats: per (b,d) mean and rstd of first_point over n -------
__global__ void stats_kernel(const float* __restrict__ fp){
    int b = blockIdx.x, d = threadIdx.x;
    const float* p = fp + (size_t)b*NTRAJ*LAT + d;
    float s = 0.f, s2 = 0.f;
#pragma unroll 4
    for (int n = 0; n < NTRAJ; n++){
        float v = p[(size_t)n*LAT];
        s += v; s2 += v*v;
    }
    float mean = s * (1.0f/NTRAJ);
    float var  = s2 - (float)NTRAJ*mean*mean;   // = diag(cov)
    g_mean[b*LAT+d] = mean;
    g_rstd[b*LAT+d] = rsqrtf(var);
}

// ---------------- gram + corrcoef -> rows [512,768) of g_x -------------------
// cov[d,e] = sum_n x_nd x_ne - N*mu_d*mu_e ; corr = cov * rstd_d * rstd_e
__global__ void gram_corr_kernel(const float* __restrict__ fp){
    int b  = blockIdx.y;
    int tr = blockIdx.x >> 2, tc = blockIdx.x & 3;   // 4x4 tiles of 64x64
    __shared__ float Xa[16][68];
    __shared__ float Xb[16][68];
    int tid = threadIdx.x;
    int ty = tid >> 4, tx = tid & 15;
    float acc[4][4] = {};
    const float* base = fp + (size_t)b*NTRAJ*LAT;
    for (int k0 = 0; k0 < NTRAJ; k0 += 16){
        int r = tid >> 4, c4 = tid & 15;
        float4 va = *(const float4*)&base[(size_t)(k0+r)*LAT + tr*64 + c4*4];
        float4 vb = *(const float4*)&base[(size_t)(k0+r)*LAT + tc*64 + c4*4];
        *(float4*)&Xa[r][c4*4] = va;
        *(float4*)&Xb[r][c4*4] = vb;
        __syncthreads();
#pragma unroll
        for (int kk = 0; kk < 16; kk++){
            float a[4], bb[4];
#pragma unroll
            for (int j = 0; j < 4; j++){ a[j] = Xa[kk][ty*4+j]; bb[j] = Xb[kk][tx*4+j]; }
#pragma unroll
            for (int i = 0; i < 4; i++)
#pragma unroll
                for (int j = 0; j < 4; j++)
                    acc[i][j] += a[i]*bb[j];
        }
        __syncthreads();
    }
#pragma unroll
    for (int i = 0; i < 4; i++){
        int d = tr*64 + ty*4 + i;
        float md = g_mean[b*LAT+d], rd = g_rstd[b*LAT+d];
#pragma unroll
        for (int j = 0; j < 4; j++){
            int e = tc*64 + tx*4 + j;
            float cov = acc[i][j] - (float)NTRAJ * md * g_mean[b*LAT+e];
            float corr = cov * rd * g_rstd[b*LAT+e];
            g_x[((size_t)b*ROWS768 + NTRAJ + d)*LAT + e] = corr;
        }
    }
}

// ---------------- init: x rows [0,512) = first_point; output t=0 slice -------
__global__ void init_kernel(const float* __restrict__ fp, float* __restrict__ out){
    int i = blockIdx.x*blockDim.x + threadIdx.x;          // < 32*512*256
    int d = i & (LAT-1);
    int n = (i >> 8) & (NTRAJ-1);
    int b = i >> 17;
    float v = fp[i];
    g_x[((size_t)b*ROWS768 + n)*LAT + d] = v;
    out[((size_t)(b*NTRAJ + n))*TT*LAT + d] = v;          // t = 0
}

// ---------------- RK4 epilogue helper (two adjacent columns) -----------------
__device__ __forceinline__ void rk4_epi(int r, int cc, float k0, float k1,
                                        int stage, float dt, int step,
                                        float* __restrict__ out){
    int idx = r*LAT + cc;
    float x0 = g_x[idx], x1 = g_x[idx+1];
    if (stage == 0){
        g_acc[idx]   = k0;               g_acc[idx+1]   = k1;
        g_stage[idx] = x0 + 0.5f*dt*k0;  g_stage[idx+1] = x1 + 0.5f*dt*k1;
    } else if (stage == 1){
        g_acc[idx]  += 2.f*k0;           g_acc[idx+1]  += 2.f*k1;
        g_stage[idx] = x0 + 0.5f*dt*k0;  g_stage[idx+1] = x1 + 0.5f*dt*k1;
    } else if (stage == 2){
        g_acc[idx]  += 2.f*k0;           g_acc[idx+1]  += 2.f*k1;
        g_stage[idx] = x0 + dt*k0;       g_stage[idx+1] = x1 + dt*k1;
    } else {
        float xn0 = x0 + dt*(1.0f/6.0f)*(g_acc[idx]   + k0);
        float xn1 = x1 + dt*(1.0f/6.0f)*(g_acc[idx+1] + k1);
        g_x[idx] = xn0; g_x[idx+1] = xn1;
        int b = r / ROWS768, n = r - b*ROWS768;
        if (n < NTRAJ){
            size_t o = (((size_t)(b*NTRAJ+n))*TT + step + 1)*LAT + cc;
            out[o] = xn0; out[o+1] = xn1;
        }
    }
}

// ---------------- fused TF32 GEMM (mma.sync m16n8k8) -------------------------
// C = A @ Bmat, fp32 accumulate, tf32 inputs (rounded on SMEM store).
// mode 0: H = tanh(C + bias)    mode 1: RK4 stage epilogue
#define BM  128
#define BN  64
#define BK  32
#define LDA 36     // pad: A-frag LDS conflict-free ((4g+t)%32 all distinct)
#define LDB 72     // pad: B-frag LDS conflict-free ((8t+g)%32 all distinct)
#define SMEM_FLOATS (2*BM*LDA + 2*BK*LDB)   // 13824 floats = 55296 B

#define MMA_TF32(C, Af, Bf) \
    asm volatile("mma.sync.aligned.m16n8k8.row.col.f32.tf32.tf32.f32 " \
        "{%0,%1,%2,%3}, {%4,%5,%6,%7}, {%8,%9}, {%0,%1,%2,%3};" \
        : "+f"((C)[0]), "+f"((C)[1]), "+f"((C)[2]), "+f"((C)[3]) \
        : "r"((Af)[0]), "r"((Af)[1]), "r"((Af)[2]), "r"((Af)[3]), \
          "r"((Bf)[0]), "r"((Bf)[1]))

__global__ void __launch_bounds__(256,2) gemm_fused(
    int asel, int lda,
    const float* __restrict__ Bmat, int ldb,
    int K, int mode,
    const float* __restrict__ bias,
    int stage, int step,
    const float* __restrict__ ts,
    float* __restrict__ out)
{
    const float* __restrict__ A = (asel==0) ? g_x : (asel==1) ? g_stage : g_H;
    extern __shared__ __align__(16) float sm[];
    float* As = sm;                  // [2][BM*LDA]
    float* Bs = sm + 2*BM*LDA;       // [2][BK*LDB]

    int tid = threadIdx.x, lane = tid & 31, wid = tid >> 5;
    int wm = wid & 3, wn = wid >> 2;           // 4x2 warps -> 32x32 warp tiles
    int g = lane >> 2, t = lane & 3;
    // N-major rasterization: blockIdx.x = col panel (for L2 reuse of A panels)
    int col0 = blockIdx.x * BN;
    int row0 = blockIdx.y * BM;

    float c[2][4][4];
#pragma unroll
    for (int mi = 0; mi < 2; mi++)
#pragma unroll
        for (int ni = 0; ni < 4; ni++)
#pragma unroll
            for (int q = 0; q < 4; q++) c[mi][ni][q] = 0.f;

    float4 ra[4], rb[2];

#define LOAD_A(kt) { \
    _Pragma("unroll") \
    for (int j = 0; j < 4; j++){ int i = tid + 256*j; int r_ = i>>3, c4 = i&7; \
        ra[j] = *(const float4*)&A[(size_t)(row0+r_)*lda + (kt)*BK + c4*4]; } }
#define LOAD_B(kt) { \
    _Pragma("unroll") \
    for (int j = 0; j < 2; j++){ int i = tid + 256*j; int r_ = i>>4, c4 = i&15; \
        rb[j] = *(const float4*)&Bmat[(size_t)((kt)*BK + r_)*ldb + col0 + c4*4]; } }
#define STORE_AB(buf) { \
    _Pragma("unroll") \
    for (int j = 0; j < 4; j++){ int i = tid + 256*j; int r_ = i>>3, c4 = i&7; \
        float* p = &As[(buf)*BM*LDA + r_*LDA + c4*4]; \
        p[0]=__uint_as_float(f2tf(ra[j].x)); p[1]=__uint_as_float(f2tf(ra[j].y)); \
        p[2]=__uint_as_float(f2tf(ra[j].z)); p[3]=__uint_as_float(f2tf(ra[j].w)); } \
    _Pragma("unroll") \
    for (int j = 0; j < 2; j++){ int i = tid + 256*j; int r_ = i>>4, c4 = i&15; \
        float* p = &Bs[(buf)*BK*LDB + r_*LDB + c4*4]; \
        p[0]=__uint_as_float(f2tf(rb[j].x)); p[1]=__uint_as_float(f2tf(rb[j].y)); \
        p[2]=__uint_as_float(f2tf(rb[j].z)); p[3]=__uint_as_float(f2tf(rb[j].w)); } }
#define COMPUTE(buf) { \
    const float* Ab = &As[(buf)*BM*LDA]; const float* Bb = &Bs[(buf)*BK*LDB]; \
    _Pragma("unroll") \
    for (int ks = 0; ks < BK; ks += 8){ \
        unsigned af[2][4]; unsigned bf[4][2]; \
        _Pragma("unroll") \
        for (int mi = 0; mi < 2; mi++){ int rb_ = wm*32 + mi*16; \
            af[mi][0]=__float_as_uint(Ab[(rb_+g  )*LDA + ks+t  ]); \
            af[mi][1]=__float_as_uint(Ab[(rb_+g+8)*LDA + ks+t  ]); \
            af[mi][2]=__float_as_uint(Ab[(rb_+g  )*LDA + ks+t+4]); \
            af[mi][3]=__float_as_uint(Ab[(rb_+g+8)*LDA + ks+t+4]); } \
        _Pragma("unroll") \
        for (int ni = 0; ni < 4; ni++){ int cb_ = wn*32 + ni*8 + g; \
            bf[ni][0]=__float_as_uint(Bb[(ks+t  )*LDB + cb_]); \
            bf[ni][1]=__float_as_uint(Bb[(ks+t+4)*LDB + cb_]); } \
        _Pragma("unroll") \
        for (int mi = 0; mi < 2; mi++) \
            _Pragma("unroll") \
            for (int ni = 0; ni < 4; ni++) \
                MMA_TF32(c[mi][ni], af[mi], bf[ni]); } }

    LOAD_A(0); LOAD_B(0);
    STORE_AB(0);
    __syncthreads();
    int KT = K / BK;
    for (int kt = 0; kt < KT; kt++){
        int cur = kt & 1;
        if (kt + 1 < KT){ LOAD_A(kt+1); LOAD_B(kt+1); }
        COMPUTE(cur);
        if (kt + 1 < KT){ STORE_AB(cur ^ 1); }
        __syncthreads();
    }

    float dt = 0.f;
    if (mode == 1) dt = __ldg(&ts[step+1]) - __ldg(&ts[step]);

#pragma unroll
    for (int mi = 0; mi < 2; mi++){
#pragma unroll
        for (int ni = 0; ni < 4; ni++){
            int r  = row0 + wm*32 + mi*16 + g;
            int cc = col0 + wn*32 + ni*8 + 2*t;
            float v00 = c[mi][ni][0], v01 = c[mi][ni][1];
            float v10 = c[mi][ni][2], v11 = c[mi][ni][3];
            if (mode == 0){
                float b0v = bias[cc], b1v = bias[cc+1];
                g_H[(size_t)r*HID + cc]       = fast_tanh(v00 + b0v);
                g_H[(size_t)r*HID + cc+1]     = fast_tanh(v01 + b1v);
                g_H[(size_t)(r+8)*HID + cc]   = fast_tanh(v10 + b0v);
                g_H[(size_t)(r+8)*HID + cc+1] = fast_tanh(v11 + b1v);
            } else {
                rk4_epi(r,   cc, v00, v01, stage, dt, step, out);
                rk4_epi(r+8, cc, v10, v11, stage, dt, step, out);
            }
        }
    }
}

// ---------------- launch -----------------------------------------------------
extern "C" void kernel_launch(void* const* d_in, const int* in_sizes, int n_in,
                              void* d_out, int out_size){
    const float* fp = (const float*)d_in[0];
    const float* ts = (const float*)d_in[1];
    const float* W1 = (const float*)d_in[2];
    const float* b1 = (const float*)d_in[3];
    const float* W2 = (const float*)d_in[4];
    float* out = (float*)d_out;
    (void)in_sizes; (void)n_in; (void)out_size;

    size_t shm = SMEM_FLOATS * sizeof(float);   // 55296 B > 48K default
    cudaFuncSetAttribute(gemm_fused, cudaFuncAttributeMaxDynamicSharedMemorySize, (int)shm);

    stats_kernel<<<B_, LAT>>>(fp);
    gram_corr_kernel<<<dim3(16, B_), 256>>>(fp);
    init_kernel<<<(B_*NTRAJ*LAT)/256, 256>>>(fp, out);

    dim3 g1(HID/BN, MTOT/BM);   // (16, 192) cols-fast for L2 A-panel reuse
    dim3 g2(LAT/BN, MTOT/BM);   // (4, 192)
    for (int step = 0; step < TT-1; step++){
        for (int s = 0; s < 4; s++){
            int asel = (s == 0) ? 0 : 1;
            // H = tanh(stage @ W1 + b1)
            gemm_fused<<<g1, 256, shm>>>(asel, LAT, W1, HID, LAT, 0, b1, 0, 0, ts, out);
            // k = H @ W2 ; RK4 stage update (fused)
            gemm_fused<<<g2, 256, shm>>>(2, HID, W2, LAT, HID, 1, nullptr, s, step, ts, out);
        }
    }
}

// round 7
// speedup vs baseline: 1.2876x; 1.2876x over previous
#include <cuda_runtime.h>
#include <cstdint>

// Problem constants
#define B_      32
#define NTRAJ   512
#define LAT     256
#define HID     1024
#define TT      10
#define ROWS768 768
#define MTOT    (B_*ROWS768)      // 24576

// ---------------- device scratch (no runtime allocation allowed) -------------
__device__ float g_x[MTOT*LAT];
__device__ float g_stage[MTOT*LAT];
__device__ float g_acc[MTOT*LAT];
__device__ float g_H[(size_t)MTOT*HID];     // 100 MB
__device__ float g_W1T[HID*LAT];            // W1^T  [1024][256]  (n-rows, K-major)
__device__ float g_W2T[LAT*HID];            // W2^T  [256][1024]
__device__ float g_mean[B_*LAT];
__device__ float g_rstd[B_*LAT];

__device__ __forceinline__ float fast_tanh(float x){
    float y; asm("tanh.approx.f32 %0, %1;" : "=f"(y) : "f"(x)); return y;
}
__device__ __forceinline__ uint32_t s2u(const void* p){
    uint32_t a;
    asm("{ .reg .u64 t; cvta.to.shared.u64 t, %1; cvt.u32.u64 %0, t; }" : "=r"(a) : "l"(p));
    return a;
}

#define CP_ASYNC16(dst, src) \
    asm volatile("cp.async.cg.shared.global [%0], [%1], 16;" :: "r"(dst), "l"(src) : "memory")
#define CP_COMMIT() asm volatile("cp.async.commit_group;" ::: "memory")
#define CP_WAIT1()  asm volatile("cp.async.wait_group 1;" ::: "memory")

#define MMA_TF32(C, Af, Bf) \
    asm volatile("mma.sync.aligned.m16n8k8.row.col.f32.tf32.tf32.f32 " \
        "{%0,%1,%2,%3}, {%4,%5,%6,%7}, {%8,%9}, {%0,%1,%2,%3};" \
        : "+f"((C)[0]), "+f"((C)[1]), "+f"((C)[2]), "+f"((C)[3]) \
        : "r"((Af)[0]), "r"((Af)[1]), "r"((Af)[2]), "r"((Af)[3]), \
          "r"((Bf)[0]), "r"((Bf)[1]))

// ---------------- small prologue kernels ------------------------------------
__global__ void stats_kernel(const float* __restrict__ fp){
    int b = blockIdx.x, d = threadIdx.x;
    const float* p = fp + (size_t)b*NTRAJ*LAT + d;
    float s = 0.f, s2 = 0.f;
#pragma unroll 4
    for (int n = 0; n < NTRAJ; n++){ float v = p[(size_t)n*LAT]; s += v; s2 += v*v; }
    float mean = s * (1.0f/NTRAJ);
    float var  = s2 - (float)NTRAJ*mean*mean;
    g_mean[b*LAT+d] = mean;
    g_rstd[b*LAT+d] = rsqrtf(var);
}

__global__ void gram_corr_kernel(const float* __restrict__ fp){
    int b  = blockIdx.y;
    int tr = blockIdx.x >> 2, tc = blockIdx.x & 3;
    __shared__ float Xa[16][68];
    __shared__ float Xb[16][68];
    int tid = threadIdx.x;
    int ty = tid >> 4, tx = tid & 15;
    float acc[4][4] = {};
    const float* base = fp + (size_t)b*NTRAJ*LAT;
    for (int k0 = 0; k0 < NTRAJ; k0 += 16){
        int r = tid >> 4, c4 = tid & 15;
        float4 va = *(const float4*)&base[(size_t)(k0+r)*LAT + tr*64 + c4*4];
        float4 vb = *(const float4*)&base[(size_t)(k0+r)*LAT + tc*64 + c4*4];
        *(float4*)&Xa[r][c4*4] = va;
        *(float4*)&Xb[r][c4*4] = vb;
        __syncthreads();
#pragma unroll
        for (int kk = 0; kk < 16; kk++){
            float a[4], bb[4];
#pragma unroll
            for (int j = 0; j < 4; j++){ a[j] = Xa[kk][ty*4+j]; bb[j] = Xb[kk][tx*4+j]; }
#pragma unroll
            for (int i = 0; i < 4; i++)
#pragma unroll
                for (int j = 0; j < 4; j++) acc[i][j] += a[i]*bb[j];
        }
        __syncthreads();
    }
#pragma unroll
    for (int i = 0; i < 4; i++){
        int d = tr*64 + ty*4 + i;
        float md = g_mean[b*LAT+d], rd = g_rstd[b*LAT+d];
#pragma unroll
        for (int j = 0; j < 4; j++){
            int e = tc*64 + tx*4 + j;
            float cov = acc[i][j] - (float)NTRAJ * md * g_mean[b*LAT+e];
            g_x[((size_t)b*ROWS768 + NTRAJ + d)*LAT + e] = cov * rd * g_rstd[b*LAT+e];
        }
    }
}

__global__ void init_kernel(const float* __restrict__ fp, float* __restrict__ out){
    int i = blockIdx.x*blockDim.x + threadIdx.x;
    int d = i & (LAT-1);
    int n = (i >> 8) & (NTRAJ-1);
    int b = i >> 17;
    float v = fp[i];
    g_x[((size_t)b*ROWS768 + n)*LAT + d] = v;
    out[((size_t)(b*NTRAJ + n))*TT*LAT + d] = v;
}

__global__ void transposeW(const float* __restrict__ W, float* __restrict__ WT, int R, int C){
    int i = blockIdx.x*256 + threadIdx.x;
    int r = i % R, cI = i / R;
    WT[(size_t)cI*R + r] = W[(size_t)r*C + cI];
}

// ---------------- tf32 mma.sync GEMM, cp.async 3-stage ----------------------
// CTA tile: BM x 128, BK=32. 8 warps as 4(m) x 2(n); warp tile (BM/4) x 64.
// Both operands in SMEM K-major, 128B rows, 16B-chunk swizzle c^(row&7):
// cp.async friendly AND conflict-free scalar LDS for A/B fragments.
// mode 0: g_H = tanh(A @ W1 + b1) ; mode 1: k = g_H @ W2, fused RK4 epilogue.

template<int BM>
__device__ __forceinline__ void load_chunk(
    uint32_t sbase, const float* __restrict__ A, const float* __restrict__ Bt,
    int row0, int col0, int K, int kc, int tid)
{
    int k0 = kc*32;
    uint32_t sB = sbase + BM*128;
#pragma unroll
    for (int i = 0; i < BM/32; i++){            // A: BM rows x 8 chunks
        int ci = tid + 256*i;
        int r = ci >> 3, c = ci & 7;
        CP_ASYNC16(sbase + (uint32_t)(r*128) + (uint32_t)((c ^ (r&7))<<4),
                   A + (size_t)(row0+r)*K + k0 + c*4);
    }
#pragma unroll
    for (int i = 0; i < 4; i++){                // B: 128 n-rows x 8 chunks
        int ci = tid + 256*i;
        int r = ci >> 3, c = ci & 7;
        CP_ASYNC16(sB + (uint32_t)(r*128) + (uint32_t)((c ^ (r&7))<<4),
                   Bt + (size_t)(col0+r)*K + k0 + c*4);
    }
}

template<int BM>
__global__ void __launch_bounds__(256,1) gemm_tc(
    int asel, int mode, int stage, int step,
    const float* __restrict__ bias, const float* __restrict__ ts,
    float* __restrict__ out)
{
    constexpr int MI = BM/64;                       // m16 tiles per warp
    constexpr int STAGE_FLOATS = BM*32 + 128*32;    // A + B tile floats
    const float* __restrict__ Amat = (asel==0) ? g_x : (asel==1) ? g_stage : g_H;
    const float* __restrict__ Bt   = (mode==0) ? g_W1T : g_W2T;
    const int K  = (mode==0) ? LAT : HID;
    const int KT = K >> 5;

    extern __shared__ float sm[];
    uint32_t sbase_u = s2u(sm);

    int tid = threadIdx.x, lane = tid & 31, wid = tid >> 5;
    int wm = wid >> 1, wn = wid & 1;                // 4 x 2 warp grid
    int g = lane >> 2, t = lane & 3;
    int row0 = blockIdx.y * BM;
    int col0 = blockIdx.x * 128;

    float c[MI][8][4];
#pragma unroll
    for (int mi = 0; mi < MI; mi++)
#pragma unroll
        for (int ni = 0; ni < 8; ni++)
#pragma unroll
            for (int q = 0; q < 4; q++) c[mi][ni][q] = 0.f;

    load_chunk<BM>(sbase_u, Amat, Bt, row0, col0, K, 0, tid); CP_COMMIT();
    load_chunk<BM>(sbase_u + STAGE_FLOATS*4, Amat, Bt, row0, col0, K, 1, tid); CP_COMMIT();

    for (int kc = 0; kc < KT; kc++){
        CP_WAIT1();
        __syncthreads();
        const float* As = sm + (kc % 3) * STAGE_FLOATS;
        const float* Bs = As + BM*32;

#pragma unroll
        for (int ks = 0; ks < 4; ks++){
            unsigned af[MI][4], bf[8][2];
            int kx = (((2*ks) ^ g) << 2) + t;       // element offset within row
#pragma unroll
            for (int mi = 0; mi < MI; mi++){
                int a0 = (wm*(BM/4) + mi*16 + g)*32 + kx;
                af[mi][0] = __float_as_uint(As[a0]);
                af[mi][1] = __float_as_uint(As[a0 + 256]);       // row +8
                af[mi][2] = __float_as_uint(As[a0 ^ 4]);         // k +4 (chunk^1)
                af[mi][3] = __float_as_uint(As[(a0 + 256) ^ 4]);
            }
#pragma unroll
            for (int ni = 0; ni < 8; ni++){
                int nb = (wn*64 + ni*8 + g)*32 + kx;
                bf[ni][0] = __float_as_uint(Bs[nb]);
                bf[ni][1] = __float_as_uint(Bs[nb ^ 4]);
            }
#pragma unroll
            for (int mi = 0; mi < MI; mi++)
#pragma unroll
                for (int ni = 0; ni < 8; ni++)
                    MMA_TF32(c[mi][ni], af[mi], bf[ni]);
        }

        if (kc + 2 < KT)
            load_chunk<BM>(sbase_u + ((kc+2)%3)*STAGE_FLOATS*4,
                           Amat, Bt, row0, col0, K, kc+2, tid);
        CP_COMMIT();
    }

    // ---------------- fused epilogue ----------------
    float dtv = 0.f;
    if (mode == 1) dtv = __ldg(&ts[step+1]) - __ldg(&ts[step]);

#pragma unroll
    for (int mi = 0; mi < MI; mi++){
#pragma unroll
        for (int half = 0; half < 2; half++){
            int rr = row0 + wm*(BM/4) + mi*16 + g + 8*half;
            if (mode == 0){
                size_t hb = (size_t)rr * HID;
#pragma unroll
                for (int ni = 0; ni < 8; ni++){
                    int cc = col0 + wn*64 + ni*8 + 2*t;
                    float2 bv = *(const float2*)&bias[cc];
                    float2 v;
                    v.x = fast_tanh(c[mi][ni][half*2+0] + bv.x);
                    v.y = fast_tanh(c[mi][ni][half*2+1] + bv.y);
                    *(float2*)&g_H[hb + cc] = v;
                }
            } else {
                int bI = rr / ROWS768, nI = rr - bI*ROWS768;
                bool wout = (stage == 3) && (nI < NTRAJ);
                size_t obase = (((size_t)(bI*NTRAJ + nI))*TT + step + 1)*LAT;
#pragma unroll
                for (int ni = 0; ni < 8; ni++){
                    int cc = col0 + wn*64 + ni*8 + 2*t;
                    size_t idx = (size_t)rr*LAT + cc;
                    float2 k2; k2.x = c[mi][ni][half*2+0]; k2.y = c[mi][ni][half*2+1];
                    float2 x2 = *(const float2*)&g_x[idx];
                    if (stage == 0){
                        *(float2*)&g_acc[idx] = k2;
                        float2 sg; sg.x = x2.x + 0.5f*dtv*k2.x; sg.y = x2.y + 0.5f*dtv*k2.y;
                        *(float2*)&g_stage[idx] = sg;
                    } else if (stage == 1 || stage == 2){
                        float2 a2 = *(const float2*)&g_acc[idx];
                        a2.x += 2.f*k2.x; a2.y += 2.f*k2.y;
                        *(float2*)&g_acc[idx] = a2;
                        float co = (stage == 1) ? 0.5f*dtv : dtv;
                        float2 sg; sg.x = x2.x + co*k2.x; sg.y = x2.y + co*k2.y;
                        *(float2*)&g_stage[idx] = sg;
                    } else {
                        float2 a2 = *(const float2*)&g_acc[idx];
                        const float c6 = dtv * (1.0f/6.0f);
                        float2 xn;
                        xn.x = x2.x + c6*(a2.x + k2.x);
                        xn.y = x2.y + c6*(a2.y + k2.y);
                        *(float2*)&g_x[idx] = xn;
                        if (wout) *(float2*)&out[obase + cc] = xn;
                    }
                }
            }
        }
    }
}

// ---------------- launch -----------------------------------------------------
extern "C" void kernel_launch(void* const* d_in, const int* in_sizes, int n_in,
                              void* d_out, int out_size){
    const float* fp = (const float*)d_in[0];
    const float* ts = (const float*)d_in[1];
    const float* W1 = (const float*)d_in[2];
    const float* b1 = (const float*)d_in[3];
    const float* W2 = (const float*)d_in[4];
    float* out = (float*)d_out;
    (void)in_sizes; (void)n_in; (void)out_size;

    const int SH256 = 3*(256*128 + 128*128);   // 147456 B
    const int SH128 = 3*(128*128 + 128*128);   //  98304 B
    cudaFuncSetAttribute(gemm_tc<256>, cudaFuncAttributeMaxDynamicSharedMemorySize, SH256);
    cudaFuncSetAttribute(gemm_tc<128>, cudaFuncAttributeMaxDynamicSharedMemorySize, SH128);

    float* w1t; cudaGetSymbolAddress((void**)&w1t, g_W1T);
    float* w2t; cudaGetSymbolAddress((void**)&w2t, g_W2T);
    transposeW<<<(LAT*HID)/256, 256>>>(W1, w1t, LAT, HID);
    transposeW<<<(HID*LAT)/256, 256>>>(W2, w2t, HID, LAT);

    stats_kernel<<<B_, LAT>>>(fp);
    gram_corr_kernel<<<dim3(16, B_), 256>>>(fp);
    init_kernel<<<(B_*NTRAJ*LAT)/256, 256>>>(fp, out);

    dim3 g1(HID/128, MTOT/256);   // (8, 96)  = 768 CTAs
    dim3 g2(LAT/128, MTOT/128);   // (2, 192) = 384 CTAs (wave balance)
    for (int step = 0; step < TT-1; step++){
        for (int s = 0; s < 4; s++){
            int asel = (s == 0) ? 0 : 1;
            gemm_tc<256><<<g1, 256, SH256>>>(asel, 0, s, step, b1, ts, out);
            gemm_tc<128><<<g2, 256, SH128>>>(2,    1, s, step, nullptr, ts, out);
        }
    }
}

// round 8
// speedup vs baseline: 1.3239x; 1.0282x over previous
#include <cuda_runtime.h>
#include <cstdint>

// Problem constants
#define B_      32
#define NTRAJ   512
#define LAT     256
#define HID     1024
#define TT      10
#define ROWS768 768
#define MTOT    (B_*ROWS768)      // 24576

// ---------------- device scratch (no runtime allocation allowed) -------------
__device__ float g_x[MTOT*LAT];
__device__ float g_stage[MTOT*LAT];
__device__ float g_acc[MTOT*LAT];
__device__ float g_H[(size_t)MTOT*HID];     // 100 MB
__device__ float g_W1T[HID*LAT];            // W1^T  [1024][256]  (n-rows, K-major)
__device__ float g_W2T[LAT*HID];            // W2^T  [256][1024]
__device__ float g_mean[B_*LAT];
__device__ float g_rstd[B_*LAT];

__device__ __forceinline__ float fast_tanh(float x){
    float y; asm("tanh.approx.f32 %0, %1;" : "=f"(y) : "f"(x)); return y;
}
__device__ __forceinline__ uint32_t s2u(const void* p){
    uint32_t a;
    asm("{ .reg .u64 t; cvta.to.shared.u64 t, %1; cvt.u32.u64 %0, t; }" : "=r"(a) : "l"(p));
    return a;
}

#define CP_ASYNC16(dst, src) \
    asm volatile("cp.async.cg.shared.global [%0], [%1], 16;" :: "r"(dst), "l"(src) : "memory")
#define CP_COMMIT() asm volatile("cp.async.commit_group;" ::: "memory")
#define CP_WAIT1()  asm volatile("cp.async.wait_group 1;" ::: "memory")

#define MMA_TF32(C, Af, Bf) \
    asm volatile("mma.sync.aligned.m16n8k8.row.col.f32.tf32.tf32.f32 " \
        "{%0,%1,%2,%3}, {%4,%5,%6,%7}, {%8,%9}, {%0,%1,%2,%3};" \
        : "+f"((C)[0]), "+f"((C)[1]), "+f"((C)[2]), "+f"((C)[3]) \
        : "r"((Af)[0]), "r"((Af)[1]), "r"((Af)[2]), "r"((Af)[3]), \
          "r"((Bf)[0]), "r"((Bf)[1]))

#define LDSM_X4(r0, r1, r2, r3, addr) \
    asm volatile("ldmatrix.sync.aligned.m8n8.x4.shared.b16 {%0,%1,%2,%3}, [%4];" \
        : "=r"(r0), "=r"(r1), "=r"(r2), "=r"(r3) : "r"(addr))

// ---------------- small prologue kernels ------------------------------------
__global__ void stats_kernel(const float* __restrict__ fp){
    int b = blockIdx.x, d = threadIdx.x;
    const float* p = fp + (size_t)b*NTRAJ*LAT + d;
    float s = 0.f, s2 = 0.f;
#pragma unroll 4
    for (int n = 0; n < NTRAJ; n++){ float v = p[(size_t)n*LAT]; s += v; s2 += v*v; }
    float mean = s * (1.0f/NTRAJ);
    float var  = s2 - (float)NTRAJ*mean*mean;
    g_mean[b*LAT+d] = mean;
    g_rstd[b*LAT+d] = rsqrtf(var);
}

__global__ void gram_corr_kernel(const float* __restrict__ fp){
    int b  = blockIdx.y;
    int tr = blockIdx.x >> 2, tc = blockIdx.x & 3;
    __shared__ float Xa[16][68];
    __shared__ float Xb[16][68];
    int tid = threadIdx.x;
    int ty = tid >> 4, tx = tid & 15;
    float acc[4][4] = {};
    const float* base = fp + (size_t)b*NTRAJ*LAT;
    for (int k0 = 0; k0 < NTRAJ; k0 += 16){
        int r = tid >> 4, c4 = tid & 15;
        float4 va = *(const float4*)&base[(size_t)(k0+r)*LAT + tr*64 + c4*4];
        float4 vb = *(const float4*)&base[(size_t)(k0+r)*LAT + tc*64 + c4*4];
        *(float4*)&Xa[r][c4*4] = va;
        *(float4*)&Xb[r][c4*4] = vb;
        __syncthreads();
#pragma unroll
        for (int kk = 0; kk < 16; kk++){
            float a[4], bb[4];
#pragma unroll
            for (int j = 0; j < 4; j++){ a[j] = Xa[kk][ty*4+j]; bb[j] = Xb[kk][tx*4+j]; }
#pragma unroll
            for (int i = 0; i < 4; i++)
#pragma unroll
                for (int j = 0; j < 4; j++) acc[i][j] += a[i]*bb[j];
        }
        __syncthreads();
    }
#pragma unroll
    for (int i = 0; i < 4; i++){
        int d = tr*64 + ty*4 + i;
        float md = g_mean[b*LAT+d], rd = g_rstd[b*LAT+d];
#pragma unroll
        for (int j = 0; j < 4; j++){
            int e = tc*64 + tx*4 + j;
            float cov = acc[i][j] - (float)NTRAJ * md * g_mean[b*LAT+e];
            g_x[((size_t)b*ROWS768 + NTRAJ + d)*LAT + e] = cov * rd * g_rstd[b*LAT+e];
        }
    }
}

__global__ void init_kernel(const float* __restrict__ fp, float* __restrict__ out){
    int i = blockIdx.x*blockDim.x + threadIdx.x;
    int d = i & (LAT-1);
    int n = (i >> 8) & (NTRAJ-1);
    int b = i >> 17;
    float v = fp[i];
    g_x[((size_t)b*ROWS768 + n)*LAT + d] = v;
    out[((size_t)(b*NTRAJ + n))*TT*LAT + d] = v;
}

__global__ void transposeW(const float* __restrict__ W, float* __restrict__ WT, int R, int C){
    int i = blockIdx.x*256 + threadIdx.x;
    int r = i % R, cI = i / R;
    WT[(size_t)cI*R + r] = W[(size_t)r*C + cI];
}

// ---------------- tf32 mma.sync GEMM, cp.async 3-stage + ldmatrix -----------
// CTA tile: BM x 128, BK=32. 8 warps as 4(m) x 2(n); warp tile (BM/4) x 64.
// Operands in SMEM K-major, 128B rows, 16B-chunk swizzle c^(r&7):
// cp.async friendly AND conflict-free for ldmatrix 8-row phases.
// Fragments loaded via ldmatrix.m8n8.x4.b16 (tf32 elements as b16 pairs).

template<int BM>
__device__ __forceinline__ void load_chunk(
    uint32_t sbase, const float* __restrict__ A, const float* __restrict__ Bt,
    int row0, int col0, int K, int kc, int tid)
{
    int k0 = kc*32;
    uint32_t sB = sbase + BM*128;
#pragma unroll
    for (int i = 0; i < BM/32; i++){            // A: BM rows x 8 chunks
        int ci = tid + 256*i;
        int r = ci >> 3, c = ci & 7;
        CP_ASYNC16(sbase + (uint32_t)(r*128) + (uint32_t)((c ^ (r&7))<<4),
                   A + (size_t)(row0+r)*K + k0 + c*4);
    }
#pragma unroll
    for (int i = 0; i < 4; i++){                // B: 128 n-rows x 8 chunks
        int ci = tid + 256*i;
        int r = ci >> 3, c = ci & 7;
        CP_ASYNC16(sB + (uint32_t)(r*128) + (uint32_t)((c ^ (r&7))<<4),
                   Bt + (size_t)(col0+r)*K + k0 + c*4);
    }
}

template<int BM>
__global__ void __launch_bounds__(256,1) gemm_tc(
    int asel, int mode, int stage, int step,
    const float* __restrict__ bias, const float* __restrict__ ts,
    float* __restrict__ out)
{
    constexpr int MI = BM/64;                       // m16 tiles per warp
    constexpr int STAGE_BYTES = (BM*32 + 128*32)*4; // A + B tile bytes
    const float* __restrict__ Amat = (asel==0) ? g_x : (asel==1) ? g_stage : g_H;
    const float* __restrict__ Bt   = (mode==0) ? g_W1T : g_W2T;
    const int K  = (mode==0) ? LAT : HID;
    const int KT = K >> 5;

    extern __shared__ float sm[];
    uint32_t sbase_u = s2u(sm);

    int tid = threadIdx.x, lane = tid & 31, wid = tid >> 5;
    int wm = wid >> 1, wn = wid & 1;                // 4 x 2 warp grid
    int g = lane >> 2, t = lane & 3;
    int row0 = blockIdx.y * BM;
    int col0 = blockIdx.x * 128;

    // ---- per-lane ldmatrix address components (stage-invariant) ----
    int s8 = lane & 7;                 // also the swizzle key (row&7)
    // A: matrix q=lane>>3: q0 rows+0-7 chk+0, q1 rows+8-15 chk+0, q2 rows+0-7 chk+1, q3 rows+8-15 chk+1
    int rowA = (lane >> 3) & 1;        // +8 rows
    int hA   = lane >> 4;              // +1 chunk
    // B: q0 n+0-7 chk0, q1 n+0-7 chk1, q2 n+8-15 chk0, q3 n+8-15 chk1
    int rowB = lane >> 4;
    int hB   = (lane >> 3) & 1;
    uint32_t offA[MI], offB[4];
#pragma unroll
    for (int mi = 0; mi < MI; mi++)
        offA[mi] = (uint32_t)((wm*(BM/4) + mi*16 + s8 + 8*rowA) * 128);
#pragma unroll
    for (int p = 0; p < 4; p++)
        offB[p] = (uint32_t)(BM*128 + (wn*64 + p*16 + s8 + 8*rowB) * 128);

    float c[MI][8][4];
#pragma unroll
    for (int mi = 0; mi < MI; mi++)
#pragma unroll
        for (int ni = 0; ni < 8; ni++)
#pragma unroll
            for (int q = 0; q < 4; q++) c[mi][ni][q] = 0.f;

    load_chunk<BM>(sbase_u, Amat, Bt, row0, col0, K, 0, tid); CP_COMMIT();
    load_chunk<BM>(sbase_u + STAGE_BYTES, Amat, Bt, row0, col0, K, 1, tid); CP_COMMIT();

    for (int kc = 0; kc < KT; kc++){
        CP_WAIT1();
        __syncthreads();
        uint32_t stU = sbase_u + (uint32_t)((kc % 3) * STAGE_BYTES);

#pragma unroll
        for (int ks = 0; ks < 4; ks++){
            uint32_t af[MI][4], bf[8][2];
            uint32_t cA = (uint32_t)((((2*ks) | hA) ^ s8) << 4);
            uint32_t cB = (uint32_t)((((2*ks) | hB) ^ s8) << 4);
#pragma unroll
            for (int mi = 0; mi < MI; mi++)
                LDSM_X4(af[mi][0], af[mi][1], af[mi][2], af[mi][3],
                        stU + offA[mi] + cA);
#pragma unroll
            for (int p = 0; p < 4; p++)
                LDSM_X4(bf[2*p][0], bf[2*p][1], bf[2*p+1][0], bf[2*p+1][1],
                        stU + offB[p] + cB);
#pragma unroll
            for (int mi = 0; mi < MI; mi++)
#pragma unroll
                for (int ni = 0; ni < 8; ni++)
                    MMA_TF32(c[mi][ni], af[mi], bf[ni]);
        }

        if (kc + 2 < KT)
            load_chunk<BM>(sbase_u + (uint32_t)(((kc+2)%3)*STAGE_BYTES),
                           Amat, Bt, row0, col0, K, kc+2, tid);
        CP_COMMIT();
    }

    // ---------------- fused epilogue ----------------
    float dtv = 0.f;
    if (mode == 1) dtv = __ldg(&ts[step+1]) - __ldg(&ts[step]);

#pragma unroll
    for (int mi = 0; mi < MI; mi++){
#pragma unroll
        for (int half = 0; half < 2; half++){
            int rr = row0 + wm*(BM/4) + mi*16 + g + 8*half;
            if (mode == 0){
                size_t hb = (size_t)rr * HID;
#pragma unroll
                for (int ni = 0; ni < 8; ni++){
                    int cc = col0 + wn*64 + ni*8 + 2*t;
                    float2 bv = *(const float2*)&bias[cc];
                    float2 v;
                    v.x = fast_tanh(c[mi][ni][half*2+0] + bv.x);
                    v.y = fast_tanh(c[mi][ni][half*2+1] + bv.y);
                    *(float2*)&g_H[hb + cc] = v;
                }
            } else {
                int bI = rr / ROWS768, nI = rr - bI*ROWS768;
                bool wout = (stage == 3) && (nI < NTRAJ);
                size_t obase = (((size_t)(bI*NTRAJ + nI))*TT + step + 1)*LAT;
#pragma unroll
                for (int ni = 0; ni < 8; ni++){
                    int cc = col0 + wn*64 + ni*8 + 2*t;
                    size_t idx = (size_t)rr*LAT + cc;
                    float2 k2; k2.x = c[mi][ni][half*2+0]; k2.y = c[mi][ni][half*2+1];
                    float2 x2 = *(const float2*)&g_x[idx];
                    if (stage == 0){
                        *(float2*)&g_acc[idx] = k2;
                        float2 sg; sg.x = x2.x + 0.5f*dtv*k2.x; sg.y = x2.y + 0.5f*dtv*k2.y;
                        *(float2*)&g_stage[idx] = sg;
                    } else if (stage == 1 || stage == 2){
                        float2 a2 = *(const float2*)&g_acc[idx];
                        a2.x += 2.f*k2.x; a2.y += 2.f*k2.y;
                        *(float2*)&g_acc[idx] = a2;
                        float co = (stage == 1) ? 0.5f*dtv : dtv;
                        float2 sg; sg.x = x2.x + co*k2.x; sg.y = x2.y + co*k2.y;
                        *(float2*)&g_stage[idx] = sg;
                    } else {
                        float2 a2 = *(const float2*)&g_acc[idx];
                        const float c6 = dtv * (1.0f/6.0f);
                        float2 xn;
                        xn.x = x2.x + c6*(a2.x + k2.x);
                        xn.y = x2.y + c6*(a2.y + k2.y);
                        *(float2*)&g_x[idx] = xn;
                        if (wout) *(float2*)&out[obase + cc] = xn;
                    }
                }
            }
        }
    }
}

// ---------------- launch -----------------------------------------------------
extern "C" void kernel_launch(void* const* d_in, const int* in_sizes, int n_in,
                              void* d_out, int out_size){
    const float* fp = (const float*)d_in[0];
    const float* ts = (const float*)d_in[1];
    const float* W1 = (const float*)d_in[2];
    const float* b1 = (const float*)d_in[3];
    const float* W2 = (const float*)d_in[4];
    float* out = (float*)d_out;
    (void)in_sizes; (void)n_in; (void)out_size;

    const int SH256 = 3*(256*128 + 128*128);   // 147456 B
    const int SH128 = 3*(128*128 + 128*128);   //  98304 B
    cudaFuncSetAttribute(gemm_tc<256>, cudaFuncAttributeMaxDynamicSharedMemorySize, SH256);
    cudaFuncSetAttribute(gemm_tc<128>, cudaFuncAttributeMaxDynamicSharedMemorySize, SH128);

    float* w1t; cudaGetSymbolAddress((void**)&w1t, g_W1T);
    float* w2t; cudaGetSymbolAddress((void**)&w2t, g_W2T);
    transposeW<<<(LAT*HID)/256, 256>>>(W1, w1t, LAT, HID);
    transposeW<<<(HID*LAT)/256, 256>>>(W2, w2t, HID, LAT);

    stats_kernel<<<B_, LAT>>>(fp);
    gram_corr_kernel<<<dim3(16, B_), 256>>>(fp);
    init_kernel<<<(B_*NTRAJ*LAT)/256, 256>>>(fp, out);

    dim3 g1(HID/128, MTOT/256);   // (8, 96)  = 768 CTAs
    dim3 g2(LAT/128, MTOT/128);   // (2, 192) = 384 CTAs (wave balance)
    for (int step = 0; step < TT-1; step++){
        for (int s = 0; s < 4; s++){
            int asel = (s == 0) ? 0 : 1;
            gemm_tc<256><<<g1, 256, SH256>>>(asel, 0, s, step, b1, ts, out);
            gemm_tc<128><<<g2, 256, SH128>>>(2,    1, s, step, nullptr, ts, out);
        }
    }
}

// round 15
// speedup vs baseline: 2.0129x; 1.5204x over previous
#include <cuda_runtime.h>
#include <cuda_fp16.h>
#include <cstdint>

// Problem constants
#define B_      32
#define NTRAJ   512
#define LAT     256
#define HID     1024
#define TT      10
#define ROWS768 768
#define MTOT    (B_*ROWS768)      // 24576

// ---------------- device scratch (no runtime allocation allowed) -------------
__device__ float  g_x[MTOT*LAT];                // fp32 state
__device__ float  g_acc[MTOT*LAT];              // fp32 RK4 accumulator
__device__ __half g_xh[MTOT*LAT];               // fp16 mirror of x (GEMM A)
__device__ __half g_stage[MTOT*LAT];            // fp16 stage input (GEMM A)
__device__ __half g_H[(size_t)MTOT*HID];        // fp16 hidden (50 MB)
__device__ __half g_W1T[HID*LAT];               // W1^T  [1024][256] K-major
__device__ __half g_W2T[LAT*HID];               // W2^T  [256][1024]
__device__ float  g_mean[B_*LAT];
__device__ float  g_rstd[B_*LAT];

__device__ __forceinline__ float fast_tanh(float x){
    float y; asm("tanh.approx.f32 %0, %1;" : "=f"(y) : "f"(x)); return y;
}
__device__ __forceinline__ uint32_t s2u(const void* p){
    uint32_t a;
    asm("{ .reg .u64 t; cvta.to.shared.u64 t, %1; cvt.u32.u64 %0, t; }" : "=r"(a) : "l"(p));
    return a;
}

#define CP_ASYNC16(dst, src) \
    asm volatile("cp.async.cg.shared.global [%0], [%1], 16;" :: "r"(dst), "l"(src) : "memory")
#define CP_COMMIT() asm volatile("cp.async.commit_group;" ::: "memory")
#define CP_WAIT1()  asm volatile("cp.async.wait_group 1;" ::: "memory")

// fp16 MMA, fp32 accumulate: D(16x8) += A(16x16) * B(16x8)
#define MMA_F16(C, Af, Bf) \
    asm volatile("mma.sync.aligned.m16n8k16.row.col.f32.f16.f16.f32 " \
        "{%0,%1,%2,%3}, {%4,%5,%6,%7}, {%8,%9}, {%0,%1,%2,%3};" \
        : "+f"((C)[0]), "+f"((C)[1]), "+f"((C)[2]), "+f"((C)[3]) \
        : "r"((Af)[0]), "r"((Af)[1]), "r"((Af)[2]), "r"((Af)[3]), \
          "r"((Bf)[0]), "r"((Bf)[1]))

#define LDSM_X4(r0, r1, r2, r3, addr) \
    asm volatile("ldmatrix.sync.aligned.m8n8.x4.shared.b16 {%0,%1,%2,%3}, [%4];" \
        : "=r"(r0), "=r"(r1), "=r"(r2), "=r"(r3) : "r"(addr))

// ---------------- small prologue kernels ------------------------------------
__global__ void stats_kernel(const float* __restrict__ fp){
    int b = blockIdx.x, d = threadIdx.x;
    const float* p = fp + (size_t)b*NTRAJ*LAT + d;
    float s = 0.f, s2 = 0.f;
#pragma unroll 4
    for (int n = 0; n < NTRAJ; n++){ float v = p[(size_t)n*LAT]; s += v; s2 += v*v; }
    float mean = s * (1.0f/NTRAJ);
    float var  = s2 - (float)NTRAJ*mean*mean;
    g_mean[b*LAT+d] = mean;
    g_rstd[b*LAT+d] = rsqrtf(var);
}

__global__ void gram_corr_kernel(const float* __restrict__ fp){
    int b  = blockIdx.y;
    int tr = blockIdx.x >> 2, tc = blockIdx.x & 3;
    __shared__ float Xa[16][68];
    __shared__ float Xb[16][68];
    int tid = threadIdx.x;
    int ty = tid >> 4, tx = tid & 15;
    float acc[4][4] = {};
    const float* base = fp + (size_t)b*NTRAJ*LAT;
    for (int k0 = 0; k0 < NTRAJ; k0 += 16){
        int r = tid >> 4, c4 = tid & 15;
        float4 va = *(const float4*)&base[(size_t)(k0+r)*LAT + tr*64 + c4*4];
        float4 vb = *(const float4*)&base[(size_t)(k0+r)*LAT + tc*64 + c4*4];
        *(float4*)&Xa[r][c4*4] = va;
        *(float4*)&Xb[r][c4*4] = vb;
        __syncthreads();
#pragma unroll
        for (int kk = 0; kk < 16; kk++){
            float a[4], bb[4];
#pragma unroll
            for (int j = 0; j < 4; j++){ a[j] = Xa[kk][ty*4+j]; bb[j] = Xb[kk][tx*4+j]; }
#pragma unroll
            for (int i = 0; i < 4; i++)
#pragma unroll
                for (int j = 0; j < 4; j++) acc[i][j] += a[i]*bb[j];
        }
        __syncthreads();
    }
#pragma unroll
    for (int i = 0; i < 4; i++){
        int d = tr*64 + ty*4 + i;
        float md = g_mean[b*LAT+d], rd = g_rstd[b*LAT+d];
#pragma unroll
        for (int j = 0; j < 4; j++){
            int e = tc*64 + tx*4 + j;
            float cov = acc[i][j] - (float)NTRAJ * md * g_mean[b*LAT+e];
            float corr = cov * rd * g_rstd[b*LAT+e];
            size_t ix = ((size_t)b*ROWS768 + NTRAJ + d)*LAT + e;
            g_x[ix]  = corr;
            g_xh[ix] = __float2half_rn(corr);
        }
    }
}

__global__ void init_kernel(const float* __restrict__ fp, float* __restrict__ out){
    int i = blockIdx.x*blockDim.x + threadIdx.x;
    int d = i & (LAT-1);
    int n = (i >> 8) & (NTRAJ-1);
    int b = i >> 17;
    float v = fp[i];
    size_t ix = ((size_t)b*ROWS768 + n)*LAT + d;
    g_x[ix]  = v;
    g_xh[ix] = __float2half_rn(v);
    out[((size_t)(b*NTRAJ + n))*TT*LAT + d] = v;
}

__global__ void transposeW(const float* __restrict__ W, __half* __restrict__ WT, int R, int C){
    int i = blockIdx.x*256 + threadIdx.x;
    int r = i % R, cI = i / R;
    WT[(size_t)cI*R + r] = __float2half_rn(W[(size_t)r*C + cI]);
}

// ---------------- fp16 mma.sync GEMM, cp.async 3-stage + ldmatrix -----------
// CTA tile: BM x 128, ktile K=64 (128B rows of fp16). 8 warps 4(m) x 2(n).
// SMEM: K-major, 128B rows, 16B-chunk swizzle c^(r&7); identical byte layout
// to the validated tf32 version, now holding halves (each row = 64 K-elems).
// mma m16n8k16: per ktile 4 ks-steps of K=16 (chunk pair 2ks|h).

template<int BM>
__device__ __forceinline__ void load_chunk(
    uint32_t sbase, const __half* __restrict__ A, const __half* __restrict__ Bt,
    int row0, int col0, int K, int kc, int tid)
{
    int k0 = kc*64;
    uint32_t sB = sbase + BM*128;
#pragma unroll
    for (int i = 0; i < BM/32; i++){            // A: BM rows x 8 chunks of 16B
        int ci = tid + 256*i;
        int r = ci >> 3, c = ci & 7;
        CP_ASYNC16(sbase + (uint32_t)(r*128) + (uint32_t)((c ^ (r&7))<<4),
                   A + (size_t)(row0+r)*K + k0 + c*8);
    }
#pragma unroll
    for (int i = 0; i < 4; i++){                // B: 128 n-rows x 8 chunks
        int ci = tid + 256*i;
        int r = ci >> 3, c = ci & 7;
        CP_ASYNC16(sB + (uint32_t)(r*128) + (uint32_t)((c ^ (r&7))<<4),
                   Bt + (size_t)(col0+r)*K + k0 + c*8);
    }
}

template<int BM>
__global__ void __launch_bounds__(256,1) gemm_tc(
    int asel, int mode, int stage, int step,
    const float* __restrict__ bias, const float* __restrict__ ts,
    float* __restrict__ out)
{
    constexpr int MI = BM/64;                       // m16 tiles per warp
    constexpr int STAGE_BYTES = (BM + 128)*128;     // A + B tile bytes
    const __half* __restrict__ Amat = (asel==0) ? g_xh : (asel==1) ? g_stage : g_H;
    const __half* __restrict__ Bt   = (mode==0) ? g_W1T : g_W2T;
    const int K  = (mode==0) ? LAT : HID;
    const int KT = K >> 6;                          // ktile covers 64 K

    extern __shared__ float sm[];
    uint32_t sbase_u = s2u(sm);

    int tid = threadIdx.x, lane = tid & 31, wid = tid >> 5;
    int wm = wid >> 1, wn = wid & 1;                // 4 x 2 warp grid
    int g = lane >> 2, t = lane & 3;
    int row0 = blockIdx.y * BM;
    int col0 = blockIdx.x * 128;

    // ---- per-lane ldmatrix address components (stage-invariant) ----
    int s8 = lane & 7;                 // swizzle key (row&7)
    int rowA = (lane >> 3) & 1;        // A: +8 rows        (a0/a1 tiles)
    int hA   = lane >> 4;              //    +1 chunk (k+8) (a2/a3 tiles)
    int rowB = lane >> 4;              // B: +8 n-rows
    int hB   = (lane >> 3) & 1;        //    +1 chunk (k+8)
    uint32_t offA[MI], offB[4];
#pragma unroll
    for (int mi = 0; mi < MI; mi++)
        offA[mi] = (uint32_t)((wm*(BM/4) + mi*16 + s8 + 8*rowA) * 128);
#pragma unroll
    for (int p = 0; p < 4; p++)
        offB[p] = (uint32_t)(BM*128 + (wn*64 + p*16 + s8 + 8*rowB) * 128);

    float c[MI][8][4];
#pragma unroll
    for (int mi = 0; mi < MI; mi++)
#pragma unroll
        for (int ni = 0; ni < 8; ni++)
#pragma unroll
            for (int q = 0; q < 4; q++) c[mi][ni][q] = 0.f;

    load_chunk<BM>(sbase_u, Amat, Bt, row0, col0, K, 0, tid); CP_COMMIT();
    load_chunk<BM>(sbase_u + STAGE_BYTES, Amat, Bt, row0, col0, K, 1, tid); CP_COMMIT();

    for (int kc = 0; kc < KT; kc++){
        CP_WAIT1();
        __syncthreads();
        uint32_t stU = sbase_u + (uint32_t)((kc % 3) * STAGE_BYTES);

#pragma unroll
        for (int ks = 0; ks < 4; ks++){             // 4 x K=16
            uint32_t af[MI][4], bf[8][2];
            uint32_t cA = (uint32_t)((((2*ks) | hA) ^ s8) << 4);
            uint32_t cB = (uint32_t)((((2*ks) | hB) ^ s8) << 4);
#pragma unroll
            for (int mi = 0; mi < MI; mi++)
                LDSM_X4(af[mi][0], af[mi][1], af[mi][2], af[mi][3],
                        stU + offA[mi] + cA);
#pragma unroll
            for (int p = 0; p < 4; p++)
                LDSM_X4(bf[2*p][0], bf[2*p][1], bf[2*p+1][0], bf[2*p+1][1],
                        stU + offB[p] + cB);
#pragma unroll
            for (int mi = 0; mi < MI; mi++)
#pragma unroll
                for (int ni = 0; ni < 8; ni++)
                    MMA_F16(c[mi][ni], af[mi], bf[ni]);
        }

        if (kc + 2 < KT)
            load_chunk<BM>(sbase_u + (uint32_t)(((kc+2)%3)*STAGE_BYTES),
                           Amat, Bt, row0, col0, K, kc+2, tid);
        CP_COMMIT();
    }

    // ---------------- fused epilogue ----------------
    float dtv = 0.f;
    if (mode == 1) dtv = __ldg(&ts[step+1]) - __ldg(&ts[step]);

#pragma unroll
    for (int mi = 0; mi < MI; mi++){
#pragma unroll
        for (int half = 0; half < 2; half++){
            int rr = row0 + wm*(BM/4) + mi*16 + g + 8*half;
            if (mode == 0){
                size_t hb = (size_t)rr * HID;
#pragma unroll
                for (int ni = 0; ni < 8; ni++){
                    int cc = col0 + wn*64 + ni*8 + 2*t;
                    float2 bv = *(const float2*)&bias[cc];
                    float vx = fast_tanh(c[mi][ni][half*2+0] + bv.x);
                    float vy = fast_tanh(c[mi][ni][half*2+1] + bv.y);
                    *(__half2*)&g_H[hb + cc] = __floats2half2_rn(vx, vy);
                }
            } else {
                int bI = rr / ROWS768, nI = rr - bI*ROWS768;
                bool wout = (stage == 3) && (nI < NTRAJ);
                size_t obase = (((size_t)(bI*NTRAJ + nI))*TT + step + 1)*LAT;
#pragma unroll
                for (int ni = 0; ni < 8; ni++){
                    int cc = col0 + wn*64 + ni*8 + 2*t;
                    size_t idx = (size_t)rr*LAT + cc;
                    float2 k2; k2.x = c[mi][ni][half*2+0]; k2.y = c[mi][ni][half*2+1];
                    float2 x2 = *(const float2*)&g_x[idx];
                    if (stage == 0){
                        *(float2*)&g_acc[idx] = k2;
                        *(__half2*)&g_stage[idx] =
                            __floats2half2_rn(x2.x + 0.5f*dtv*k2.x, x2.y + 0.5f*dtv*k2.y);
                    } else if (stage == 1 || stage == 2){
                        float2 a2 = *(const float2*)&g_acc[idx];
                        a2.x += 2.f*k2.x; a2.y += 2.f*k2.y;
                        *(float2*)&g_acc[idx] = a2;
                        float co = (stage == 1) ? 0.5f*dtv : dtv;
                        *(__half2*)&g_stage[idx] =
                            __floats2half2_rn(x2.x + co*k2.x, x2.y + co*k2.y);
                    } else {
                        float2 a2 = *(const float2*)&g_acc[idx];
                        const float c6 = dtv * (1.0f/6.0f);
                        float2 xn;
                        xn.x = x2.x + c6*(a2.x + k2.x);
                        xn.y = x2.y + c6*(a2.y + k2.y);
                        *(float2*)&g_x[idx] = xn;
                        *(__half2*)&g_xh[idx] = __floats2half2_rn(xn.x, xn.y);
                        if (wout) *(float2*)&out[obase + cc] = xn;
                    }
                }
            }
        }
    }
}

// ---------------- launch -----------------------------------------------------
extern "C" void kernel_launch(void* const* d_in, const int* in_sizes, int n_in,
                              void* d_out, int out_size){
    const float* fp = (const float*)d_in[0];
    const float* ts = (const float*)d_in[1];
    const float* W1 = (const float*)d_in[2];
    const float* b1 = (const float*)d_in[3];
    const float* W2 = (const float*)d_in[4];
    float* out = (float*)d_out;
    (void)in_sizes; (void)n_in; (void)out_size;

    const int SH256 = 3*(256 + 128)*128;   // 147456 B
    const int SH128 = 3*(128 + 128)*128;   //  98304 B
    cudaFuncSetAttribute(gemm_tc<256>, cudaFuncAttributeMaxDynamicSharedMemorySize, SH256);
    cudaFuncSetAttribute(gemm_tc<128>, cudaFuncAttributeMaxDynamicSharedMemorySize, SH128);

    __half* w1t; cudaGetSymbolAddress((void**)&w1t, g_W1T);
    __half* w2t; cudaGetSymbolAddress((void**)&w2t, g_W2T);
    transposeW<<<(LAT*HID)/256, 256>>>(W1, w1t, LAT, HID);
    transposeW<<<(HID*LAT)/256, 256>>>(W2, w2t, HID, LAT);

    stats_kernel<<<B_, LAT>>>(fp);
    gram_corr_kernel<<<dim3(16, B_), 256>>>(fp);
    init_kernel<<<(B_*NTRAJ*LAT)/256, 256>>>(fp, out);

    dim3 g1(HID/128, MTOT/256);   // (8, 96)  = 768 CTAs
    dim3 g2(LAT/128, MTOT/128);   // (2, 192) = 384 CTAs (wave balance)
    for (int step = 0; step < TT-1; step++){
        for (int s = 0; s < 4; s++){
            int asel = (s == 0) ? 0 : 1;
            gemm_tc<256><<<g1, 256, SH256>>>(asel, 0, s, step, b1, ts, out);
            gemm_tc<128><<<g2, 256, SH128>>>(2,    1, s, step, nullptr, ts, out);
        }
    }
}

// round 16
// speedup vs baseline: 3.1964x; 1.5880x over previous
#include <cuda_runtime.h>
#include <cuda_fp16.h>
#include <cstdint>

// Problem constants
#define B_      32
#define NTRAJ   512
#define LAT     256
#define HID     1024
#define TT      10
// Only trajectory rows matter: corrcoef rows never reach the output
// (the ODE func is row-independent; reference slices [:, :, :n_traj, :]).
#define MTOT    (B_*NTRAJ)        // 16384 rows of ODE state

// ---------------- device scratch (no runtime allocation allowed) -------------
__device__ float  g_x[MTOT*LAT];                // fp32 state
__device__ float  g_acc[MTOT*LAT];              // fp32 RK4 accumulator
__device__ __half g_xh[MTOT*LAT];               // fp16 mirror of x (GEMM A)
__device__ __half g_stage[MTOT*LAT];            // fp16 stage input (GEMM A)
__device__ __half g_H[(size_t)MTOT*HID];        // fp16 hidden (32 MB)
__device__ __half g_W1T[HID*LAT];               // W1^T  [1024][256] K-major
__device__ __half g_W2T[LAT*HID];               // W2^T  [256][1024]

__device__ __forceinline__ float fast_tanh(float x){
    float y; asm("tanh.approx.f32 %0, %1;" : "=f"(y) : "f"(x)); return y;
}
__device__ __forceinline__ uint32_t s2u(const void* p){
    uint32_t a;
    asm("{ .reg .u64 t; cvta.to.shared.u64 t, %1; cvt.u32.u64 %0, t; }" : "=r"(a) : "l"(p));
    return a;
}

#define CP_ASYNC16(dst, src) \
    asm volatile("cp.async.cg.shared.global [%0], [%1], 16;" :: "r"(dst), "l"(src) : "memory")
#define CP_COMMIT() asm volatile("cp.async.commit_group;" ::: "memory")
#define CP_WAIT1()  asm volatile("cp.async.wait_group 1;" ::: "memory")

// fp16 MMA, fp32 accumulate: D(16x8) += A(16x16) * B(16x8)
#define MMA_F16(C, Af, Bf) \
    asm volatile("mma.sync.aligned.m16n8k16.row.col.f32.f16.f16.f32 " \
        "{%0,%1,%2,%3}, {%4,%5,%6,%7}, {%8,%9}, {%0,%1,%2,%3};" \
        : "+f"((C)[0]), "+f"((C)[1]), "+f"((C)[2]), "+f"((C)[3]) \
        : "r"((Af)[0]), "r"((Af)[1]), "r"((Af)[2]), "r"((Af)[3]), \
          "r"((Bf)[0]), "r"((Bf)[1]))

#define LDSM_X4(r0, r1, r2, r3, addr) \
    asm volatile("ldmatrix.sync.aligned.m8n8.x4.shared.b16 {%0,%1,%2,%3}, [%4];" \
        : "=r"(r0), "=r"(r1), "=r"(r2), "=r"(r3) : "r"(addr))

// ---------------- prologue kernels ------------------------------------------
// State rows are exactly first_point rows (b*512+n): straight copy.
__global__ void init_kernel(const float* __restrict__ fp, float* __restrict__ out){
    int i = blockIdx.x*blockDim.x + threadIdx.x;          // < MTOT*LAT
    int d = i & (LAT-1);
    int rn = i >> 8;                                      // b*NTRAJ + n
    float v = fp[i];
    g_x[i]  = v;
    g_xh[i] = __float2half_rn(v);
    out[((size_t)rn*TT)*LAT + d] = v;                     // t = 0 slice
}

__global__ void transposeW(const float* __restrict__ W, __half* __restrict__ WT, int R, int C){
    int i = blockIdx.x*256 + threadIdx.x;
    int r = i % R, cI = i / R;
    WT[(size_t)cI*R + r] = __float2half_rn(W[(size_t)r*C + cI]);
}

// ---------------- fp16 mma.sync GEMM, cp.async 3-stage + ldmatrix -----------
// CTA tile: BM x 128, ktile K=64 (128B rows of fp16). 8 warps 4(m) x 2(n).
// SMEM: K-major, 128B rows, 16B-chunk swizzle c^(r&7).
// mode 0: g_H = tanh(A @ W1 + b1) ; mode 1: k = g_H @ W2, fused RK4 epilogue.

template<int BM>
__device__ __forceinline__ void load_chunk(
    uint32_t sbase, const __half* __restrict__ A, const __half* __restrict__ Bt,
    int row0, int col0, int K, int kc, int tid)
{
    int k0 = kc*64;
    uint32_t sB = sbase + BM*128;
#pragma unroll
    for (int i = 0; i < BM/32; i++){            // A: BM rows x 8 chunks of 16B
        int ci = tid + 256*i;
        int r = ci >> 3, c = ci & 7;
        CP_ASYNC16(sbase + (uint32_t)(r*128) + (uint32_t)((c ^ (r&7))<<4),
                   A + (size_t)(row0+r)*K + k0 + c*8);
    }
#pragma unroll
    for (int i = 0; i < 4; i++){                // B: 128 n-rows x 8 chunks
        int ci = tid + 256*i;
        int r = ci >> 3, c = ci & 7;
        CP_ASYNC16(sB + (uint32_t)(r*128) + (uint32_t)((c ^ (r&7))<<4),
                   Bt + (size_t)(col0+r)*K + k0 + c*8);
    }
}

template<int BM>
__global__ void __launch_bounds__(256,1) gemm_tc(
    int asel, int mode, int stage, int step,
    const float* __restrict__ bias, const float* __restrict__ ts,
    float* __restrict__ out)
{
    constexpr int MI = BM/64;                       // m16 tiles per warp
    constexpr int STAGE_BYTES = (BM + 128)*128;     // A + B tile bytes
    const __half* __restrict__ Amat = (asel==0) ? g_xh : (asel==1) ? g_stage : g_H;
    const __half* __restrict__ Bt   = (mode==0) ? g_W1T : g_W2T;
    const int K  = (mode==0) ? LAT : HID;
    const int KT = K >> 6;                          // ktile covers 64 K

    extern __shared__ float sm[];
    uint32_t sbase_u = s2u(sm);

    int tid = threadIdx.x, lane = tid & 31, wid = tid >> 5;
    int wm = wid >> 1, wn = wid & 1;                // 4 x 2 warp grid
    int g = lane >> 2, t = lane & 3;
    int row0 = blockIdx.y * BM;
    int col0 = blockIdx.x * 128;

    // ---- per-lane ldmatrix address components (stage-invariant) ----
    int s8 = lane & 7;                 // swizzle key (row&7)
    int rowA = (lane >> 3) & 1;        // A: +8 rows        (a0/a1 tiles)
    int hA   = lane >> 4;              //    +1 chunk (k+8) (a2/a3 tiles)
    int rowB = lane >> 4;              // B: +8 n-rows
    int hB   = (lane >> 3) & 1;        //    +1 chunk (k+8)
    uint32_t offA[MI], offB[4];
#pragma unroll
    for (int mi = 0; mi < MI; mi++)
        offA[mi] = (uint32_t)((wm*(BM/4) + mi*16 + s8 + 8*rowA) * 128);
#pragma unroll
    for (int p = 0; p < 4; p++)
        offB[p] = (uint32_t)(BM*128 + (wn*64 + p*16 + s8 + 8*rowB) * 128);

    float c[MI][8][4];
#pragma unroll
    for (int mi = 0; mi < MI; mi++)
#pragma unroll
        for (int ni = 0; ni < 8; ni++)
#pragma unroll
            for (int q = 0; q < 4; q++) c[mi][ni][q] = 0.f;

    load_chunk<BM>(sbase_u, Amat, Bt, row0, col0, K, 0, tid); CP_COMMIT();
    load_chunk<BM>(sbase_u + STAGE_BYTES, Amat, Bt, row0, col0, K, 1, tid); CP_COMMIT();

    for (int kc = 0; kc < KT; kc++){
        CP_WAIT1();
        __syncthreads();
        uint32_t stU = sbase_u + (uint32_t)((kc % 3) * STAGE_BYTES);

#pragma unroll
        for (int ks = 0; ks < 4; ks++){             // 4 x K=16
            uint32_t af[MI][4], bf[8][2];
            uint32_t cA = (uint32_t)((((2*ks) | hA) ^ s8) << 4);
            uint32_t cB = (uint32_t)((((2*ks) | hB) ^ s8) << 4);
#pragma unroll
            for (int mi = 0; mi < MI; mi++)
                LDSM_X4(af[mi][0], af[mi][1], af[mi][2], af[mi][3],
                        stU + offA[mi] + cA);
#pragma unroll
            for (int p = 0; p < 4; p++)
                LDSM_X4(bf[2*p][0], bf[2*p][1], bf[2*p+1][0], bf[2*p+1][1],
                        stU + offB[p] + cB);
#pragma unroll
            for (int mi = 0; mi < MI; mi++)
#pragma unroll
                for (int ni = 0; ni < 8; ni++)
                    MMA_F16(c[mi][ni], af[mi], bf[ni]);
        }

        if (kc + 2 < KT)
            load_chunk<BM>(sbase_u + (uint32_t)(((kc+2)%3)*STAGE_BYTES),
                           Amat, Bt, row0, col0, K, kc+2, tid);
        CP_COMMIT();
    }

    // ---------------- fused epilogue ----------------
    float dtv = 0.f;
    if (mode == 1) dtv = __ldg(&ts[step+1]) - __ldg(&ts[step]);

#pragma unroll
    for (int mi = 0; mi < MI; mi++){
#pragma unroll
        for (int half = 0; half < 2; half++){
            int rr = row0 + wm*(BM/4) + mi*16 + g + 8*half;
            if (mode == 0){
                size_t hb = (size_t)rr * HID;
#pragma unroll
                for (int ni = 0; ni < 8; ni++){
                    int cc = col0 + wn*64 + ni*8 + 2*t;
                    float2 bv = *(const float2*)&bias[cc];
                    float vx = fast_tanh(c[mi][ni][half*2+0] + bv.x);
                    float vy = fast_tanh(c[mi][ni][half*2+1] + bv.y);
                    *(__half2*)&g_H[hb + cc] = __floats2half2_rn(vx, vy);
                }
            } else {
                // rr = b*NTRAJ + n directly (all rows are trajectory rows)
                size_t obase = (((size_t)rr)*TT + step + 1)*LAT;
#pragma unroll
                for (int ni = 0; ni < 8; ni++){
                    int cc = col0 + wn*64 + ni*8 + 2*t;
                    size_t idx = (size_t)rr*LAT + cc;
                    float2 k2; k2.x = c[mi][ni][half*2+0]; k2.y = c[mi][ni][half*2+1];
                    float2 x2 = *(const float2*)&g_x[idx];
                    if (stage == 0){
                        *(float2*)&g_acc[idx] = k2;
                        *(__half2*)&g_stage[idx] =
                            __floats2half2_rn(x2.x + 0.5f*dtv*k2.x, x2.y + 0.5f*dtv*k2.y);
                    } else if (stage == 1 || stage == 2){
                        float2 a2 = *(const float2*)&g_acc[idx];
                        a2.x += 2.f*k2.x; a2.y += 2.f*k2.y;
                        *(float2*)&g_acc[idx] = a2;
                        float co = (stage == 1) ? 0.5f*dtv : dtv;
                        *(__half2*)&g_stage[idx] =
                            __floats2half2_rn(x2.x + co*k2.x, x2.y + co*k2.y);
                    } else {
                        float2 a2 = *(const float2*)&g_acc[idx];
                        const float c6 = dtv * (1.0f/6.0f);
                        float2 xn;
                        xn.x = x2.x + c6*(a2.x + k2.x);
                        xn.y = x2.y + c6*(a2.y + k2.y);
                        *(float2*)&g_x[idx] = xn;
                        *(__half2*)&g_xh[idx] = __floats2half2_rn(xn.x, xn.y);
                        *(float2*)&out[obase + cc] = xn;
                    }
                }
            }
        }
    }
}

// ---------------- launch -----------------------------------------------------
extern "C" void kernel_launch(void* const* d_in, const int* in_sizes, int n_in,
                              void* d_out, int out_size){
    const float* fp = (const float*)d_in[0];
    const float* ts = (const float*)d_in[1];
    const float* W1 = (const float*)d_in[2];
    const float* b1 = (const float*)d_in[3];
    const float* W2 = (const float*)d_in[4];
    float* out = (float*)d_out;
    (void)in_sizes; (void)n_in; (void)out_size;

    const int SH256 = 3*(256 + 128)*128;   // 147456 B
    const int SH128 = 3*(128 + 128)*128;   //  98304 B
    cudaFuncSetAttribute(gemm_tc<256>, cudaFuncAttributeMaxDynamicSharedMemorySize, SH256);
    cudaFuncSetAttribute(gemm_tc<128>, cudaFuncAttributeMaxDynamicSharedMemorySize, SH128);

    __half* w1t; cudaGetSymbolAddress((void**)&w1t, g_W1T);
    __half* w2t; cudaGetSymbolAddress((void**)&w2t, g_W2T);
    transposeW<<<(LAT*HID)/256, 256>>>(W1, w1t, LAT, HID);
    transposeW<<<(HID*LAT)/256, 256>>>(W2, w2t, HID, LAT);

    init_kernel<<<(MTOT*LAT)/256, 256>>>(fp, out);

    dim3 g1(HID/128, MTOT/256);   // (8, 64)  = 512 CTAs
    dim3 g2(LAT/128, MTOT/128);   // (2, 128) = 256 CTAs
    for (int step = 0; step < TT-1; step++){
        for (int s = 0; s < 4; s++){
            int asel = (s == 0) ? 0 : 1;
            gemm_tc<256><<<g1, 256, SH256>>>(asel, 0, s, step, b1, ts, out);
            gemm_tc<128><<<g2, 256, SH128>>>(2,    1, s, step, nullptr, ts, out);
        }
    }
}

// round 17
// speedup vs baseline: 3.8182x; 1.1945x over previous
#include <cuda_runtime.h>
#include <cuda_fp16.h>
#include <cstdint>

// Problem constants
#define B_      32
#define NTRAJ   512
#define LAT     256
#define HID     1024
#define TT      10
// Only trajectory rows matter: corrcoef rows never reach the output
// (the ODE func is row-independent; reference slices [:, :, :n_traj, :]).
#define MTOT    (B_*NTRAJ)        // 16384 rows of ODE state

// ---------------- device scratch (no runtime allocation allowed) -------------
__device__ float  g_x[MTOT*LAT];                // fp32 state
__device__ float  g_acc[MTOT*LAT];              // fp32 RK4 accumulator
__device__ __half g_xh[MTOT*LAT];               // fp16 mirror of x (GEMM A)
__device__ __half g_stage[MTOT*LAT];            // fp16 stage input (GEMM A)
__device__ __half g_H[(size_t)MTOT*HID];        // fp16 hidden (32 MB)
__device__ __half g_W1T[HID*LAT];               // W1^T  [1024][256] K-major
__device__ __half g_W2T[LAT*HID];               // W2^T  [256][1024]

__device__ __forceinline__ float fast_tanh(float x){
    float y; asm("tanh.approx.f32 %0, %1;" : "=f"(y) : "f"(x)); return y;
}
__device__ __forceinline__ uint32_t s2u(const void* p){
    uint32_t a;
    asm("{ .reg .u64 t; cvta.to.shared.u64 t, %1; cvt.u32.u64 %0, t; }" : "=r"(a) : "l"(p));
    return a;
}

#define CP_ASYNC16(dst, src) \
    asm volatile("cp.async.cg.shared.global [%0], [%1], 16;" :: "r"(dst), "l"(src) : "memory")
#define CP_COMMIT() asm volatile("cp.async.commit_group;" ::: "memory")
#define CP_WAIT1()  asm volatile("cp.async.wait_group 1;" ::: "memory")

// fp16 MMA, fp32 accumulate: D(16x8) += A(16x16) * B(16x8)
#define MMA_F16(C, Af, Bf) \
    asm volatile("mma.sync.aligned.m16n8k16.row.col.f32.f16.f16.f32 " \
        "{%0,%1,%2,%3}, {%4,%5,%6,%7}, {%8,%9}, {%0,%1,%2,%3};" \
        : "+f"((C)[0]), "+f"((C)[1]), "+f"((C)[2]), "+f"((C)[3]) \
        : "r"((Af)[0]), "r"((Af)[1]), "r"((Af)[2]), "r"((Af)[3]), \
          "r"((Bf)[0]), "r"((Bf)[1]))

#define LDSM_X4(r0, r1, r2, r3, addr) \
    asm volatile("ldmatrix.sync.aligned.m8n8.x4.shared.b16 {%0,%1,%2,%3}, [%4];" \
        : "=r"(r0), "=r"(r1), "=r"(r2), "=r"(r3) : "r"(addr))

// ---------------- prologue kernels ------------------------------------------
// State rows are exactly first_point rows (b*512+n): straight copy.
__global__ void init_kernel(const float* __restrict__ fp, float* __restrict__ out){
    int i = blockIdx.x*blockDim.x + threadIdx.x;          // < MTOT*LAT
    int d = i & (LAT-1);
    int rn = i >> 8;                                      // b*NTRAJ + n
    float v = fp[i];
    g_x[i]  = v;
    g_xh[i] = __float2half_rn(v);
    out[((size_t)rn*TT)*LAT + d] = v;                     // t = 0 slice
}

__global__ void transposeW(const float* __restrict__ W, __half* __restrict__ WT, int R, int C){
    int i = blockIdx.x*256 + threadIdx.x;
    int r = i % R, cI = i / R;
    WT[(size_t)cI*R + r] = __float2half_rn(W[(size_t)r*C + cI]);
}

// ---------------- fp16 mma.sync GEMM, cp.async 3-stage + ldmatrix -----------
// CTA tile: 128 x 128, ktile K=64 (128B rows of fp16). 128 threads,
// 4 warps as 2(m) x 2(n), warp tile 64x64. 2 CTAs/SM: independent CTAs
// hide each other's ktile-boundary barrier + cp.async stalls.
// SMEM: K-major, 128B rows, 16B-chunk swizzle c^(r&7).
// mode 0: g_H = tanh(A @ W1 + b1) ; mode 1: k = g_H @ W2, fused RK4 epilogue.

#define BM 128
#define STAGE_BYTES ((BM + 128)*128)   // 32768: A tile + B tile
#define SMEM_TOTAL  (3*STAGE_BYTES)    // 98304 per CTA -> 2 CTAs/SM

__device__ __forceinline__ void load_chunk(
    uint32_t sbase, const __half* __restrict__ A, const __half* __restrict__ Bt,
    int row0, int col0, int K, int kc, int tid)
{
    int k0 = kc*64;
    uint32_t sB = sbase + BM*128;
#pragma unroll
    for (int i = 0; i < 8; i++){                // A: 128 rows x 8 chunks of 16B
        int ci = tid + 128*i;
        int r = ci >> 3, c = ci & 7;
        CP_ASYNC16(sbase + (uint32_t)(r*128) + (uint32_t)((c ^ (r&7))<<4),
                   A + (size_t)(row0+r)*K + k0 + c*8);
    }
#pragma unroll
    for (int i = 0; i < 8; i++){                // B: 128 n-rows x 8 chunks
        int ci = tid + 128*i;
        int r = ci >> 3, c = ci & 7;
        CP_ASYNC16(sB + (uint32_t)(r*128) + (uint32_t)((c ^ (r&7))<<4),
                   Bt + (size_t)(col0+r)*K + k0 + c*8);
    }
}

__global__ void __launch_bounds__(128,2) gemm_tc(
    int asel, int mode, int stage, int step,
    const float* __restrict__ bias, const float* __restrict__ ts,
    float* __restrict__ out)
{
    const __half* __restrict__ Amat = (asel==0) ? g_xh : (asel==1) ? g_stage : g_H;
    const __half* __restrict__ Bt   = (mode==0) ? g_W1T : g_W2T;
    const int K  = (mode==0) ? LAT : HID;
    const int KT = K >> 6;                          // ktile covers 64 K

    extern __shared__ float sm[];
    uint32_t sbase_u = s2u(sm);

    int tid = threadIdx.x, lane = tid & 31, wid = tid >> 5;
    int wm = wid >> 1, wn = wid & 1;                // 2 x 2 warp grid
    int g = lane >> 2, t = lane & 3;
    int row0 = blockIdx.y * BM;
    int col0 = blockIdx.x * 128;

    // ---- per-lane ldmatrix address components (stage-invariant) ----
    int s8 = lane & 7;                 // swizzle key (row&7)
    int rowA = (lane >> 3) & 1;        // A: +8 rows        (a0/a1 tiles)
    int hA   = lane >> 4;              //    +1 chunk (k+8) (a2/a3 tiles)
    int rowB = lane >> 4;              // B: +8 n-rows
    int hB   = (lane >> 3) & 1;        //    +1 chunk (k+8)
    uint32_t offA[4], offB[4];
#pragma unroll
    for (int mi = 0; mi < 4; mi++)
        offA[mi] = (uint32_t)((wm*64 + mi*16 + s8 + 8*rowA) * 128);
#pragma unroll
    for (int p = 0; p < 4; p++)
        offB[p] = (uint32_t)(BM*128 + (wn*64 + p*16 + s8 + 8*rowB) * 128);

    float c[4][8][4];
#pragma unroll
    for (int mi = 0; mi < 4; mi++)
#pragma unroll
        for (int ni = 0; ni < 8; ni++)
#pragma unroll
            for (int q = 0; q < 4; q++) c[mi][ni][q] = 0.f;

    load_chunk(sbase_u, Amat, Bt, row0, col0, K, 0, tid); CP_COMMIT();
    load_chunk(sbase_u + STAGE_BYTES, Amat, Bt, row0, col0, K, 1, tid); CP_COMMIT();

    for (int kc = 0; kc < KT; kc++){
        CP_WAIT1();
        __syncthreads();
        uint32_t stU = sbase_u + (uint32_t)((kc % 3) * STAGE_BYTES);

#pragma unroll
        for (int ks = 0; ks < 4; ks++){             // 4 x K=16
            uint32_t af[4][4], bf[8][2];
            uint32_t cA = (uint32_t)((((2*ks) | hA) ^ s8) << 4);
            uint32_t cB = (uint32_t)((((2*ks) | hB) ^ s8) << 4);
#pragma unroll
            for (int mi = 0; mi < 4; mi++)
                LDSM_X4(af[mi][0], af[mi][1], af[mi][2], af[mi][3],
                        stU + offA[mi] + cA);
#pragma unroll
            for (int p = 0; p < 4; p++)
                LDSM_X4(bf[2*p][0], bf[2*p][1], bf[2*p+1][0], bf[2*p+1][1],
                        stU + offB[p] + cB);
#pragma unroll
            for (int mi = 0; mi < 4; mi++)
#pragma unroll
                for (int ni = 0; ni < 8; ni++)
                    MMA_F16(c[mi][ni], af[mi], bf[ni]);
        }

        if (kc + 2 < KT)
            load_chunk(sbase_u + (uint32_t)(((kc+2)%3)*STAGE_BYTES),
                       Amat, Bt, row0, col0, K, kc+2, tid);
        CP_COMMIT();
    }

    // ---------------- fused epilogue ----------------
    float dtv = 0.f;
    if (mode == 1) dtv = __ldg(&ts[step+1]) - __ldg(&ts[step]);

#pragma unroll
    for (int mi = 0; mi < 4; mi++){
#pragma unroll
        for (int half = 0; half < 2; half++){
            int rr = row0 + wm*64 + mi*16 + g + 8*half;
            if (mode == 0){
                size_t hb = (size_t)rr * HID;
#pragma unroll
                for (int ni = 0; ni < 8; ni++){
                    int cc = col0 + wn*64 + ni*8 + 2*t;
                    float2 bv = *(const float2*)&bias[cc];
                    float vx = fast_tanh(c[mi][ni][half*2+0] + bv.x);
                    float vy = fast_tanh(c[mi][ni][half*2+1] + bv.y);
                    *(__half2*)&g_H[hb + cc] = __floats2half2_rn(vx, vy);
                }
            } else {
                // rr = b*NTRAJ + n directly (all rows are trajectory rows)
                size_t obase = (((size_t)rr)*TT + step + 1)*LAT;
#pragma unroll
                for (int ni = 0; ni < 8; ni++){
                    int cc = col0 + wn*64 + ni*8 + 2*t;
                    size_t idx = (size_t)rr*LAT + cc;
                    float2 k2; k2.x = c[mi][ni][half*2+0]; k2.y = c[mi][ni][half*2+1];
                    float2 x2 = *(const float2*)&g_x[idx];
                    if (stage == 0){
                        *(float2*)&g_acc[idx] = k2;
                        *(__half2*)&g_stage[idx] =
                            __floats2half2_rn(x2.x + 0.5f*dtv*k2.x, x2.y + 0.5f*dtv*k2.y);
                    } else if (stage == 1 || stage == 2){
                        float2 a2 = *(const float2*)&g_acc[idx];
                        a2.x += 2.f*k2.x; a2.y += 2.f*k2.y;
                        *(float2*)&g_acc[idx] = a2;
                        float co = (stage == 1) ? 0.5f*dtv : dtv;
                        *(__half2*)&g_stage[idx] =
                            __floats2half2_rn(x2.x + co*k2.x, x2.y + co*k2.y);
                    } else {
                        float2 a2 = *(const float2*)&g_acc[idx];
                        const float c6 = dtv * (1.0f/6.0f);
                        float2 xn;
                        xn.x = x2.x + c6*(a2.x + k2.x);
                        xn.y = x2.y + c6*(a2.y + k2.y);
                        *(float2*)&g_x[idx] = xn;
                        *(__half2*)&g_xh[idx] = __floats2half2_rn(xn.x, xn.y);
                        *(float2*)&out[obase + cc] = xn;
                    }
                }
            }
        }
    }
}

// ---------------- launch -----------------------------------------------------
extern "C" void kernel_launch(void* const* d_in, const int* in_sizes, int n_in,
                              void* d_out, int out_size){
    const float* fp = (const float*)d_in[0];
    const float* ts = (const float*)d_in[1];
    const float* W1 = (const float*)d_in[2];
    const float* b1 = (const float*)d_in[3];
    const float* W2 = (const float*)d_in[4];
    float* out = (float*)d_out;
    (void)in_sizes; (void)n_in; (void)out_size;

    cudaFuncSetAttribute(gemm_tc, cudaFuncAttributeMaxDynamicSharedMemorySize, SMEM_TOTAL);

    __half* w1t; cudaGetSymbolAddress((void**)&w1t, g_W1T);
    __half* w2t; cudaGetSymbolAddress((void**)&w2t, g_W2T);
    transposeW<<<(LAT*HID)/256, 256>>>(W1, w1t, LAT, HID);
    transposeW<<<(HID*LAT)/256, 256>>>(W2, w2t, HID, LAT);

    init_kernel<<<(MTOT*LAT)/256, 256>>>(fp, out);

    dim3 g1(HID/128, MTOT/128);   // (8, 128) = 1024 CTAs
    dim3 g2(LAT/128, MTOT/128);   // (2, 128) =  256 CTAs
    for (int step = 0; step < TT-1; step++){
        for (int s = 0; s < 4; s++){
            int asel = (s == 0) ? 0 : 1;
            gemm_tc<<<g1, 128, SMEM_TOTAL>>>(asel, 0, s, step, b1, ts, out);
            gemm_tc<<<g2, 128, SMEM_TOTAL>>>(2,    1, s, step, nullptr, ts, out);
        }
    }
}